// round 16
// baseline (speedup 1.0000x reference)
#include <cuda_runtime.h>
#include <cuda_fp16.h>
#include <stdint.h>
#include <math.h>

#define BSZ 64
#define NAG 512
#define OBS 128
#define HID 256
#define MSG 128
#define NACT 16
#define ROWS (BSZ*NAG)   // 32768

// ---------------- scratch (device globals, fp16) ----------------
__device__ __align__(16) __half g_enc[(size_t)ROWS*HID];
__device__ __align__(16) __half g_msgq[(size_t)ROWS*256];   // cols 0-127 msg (Q half unused now)
__device__ __align__(16) __half g_qext[(size_t)ROWS*256];   // 0-127 Q*imp/sqrt(128), 128-255 obs_scaled
__device__ __align__(16) __half g_kext[(size_t)ROWS*256];   // 0-127 K*imp,          128-255 obs_scaled
__device__ __align__(16) __half g_obs[(size_t)ROWS*OBS];
__device__ float g_imp[ROWS];
__device__ __align__(16) __half g_vT[(size_t)BSZ*MSG*NAG];  // [b][d][k]
__device__ __align__(16) __half g_agg[(size_t)ROWS*MSG];
__device__ float g_x[(size_t)ROWS*HID];
__device__ float g_bcat[256];
__device__ float g_bkv[256];
__device__ __align__(16) __half g_WeT[256*128];
__device__ __align__(16) __half g_WcatT[256*256];
__device__ __align__(16) __half g_WkvT[256*128];
__device__ __align__(16) __half g_WpT[256*384];

// ---------------- helpers ----------------
__device__ __forceinline__ uint32_t smem_u32(const void* p){
    uint32_t a;
    asm("{ .reg .u64 t; cvta.to.shared.u64 t, %1; cvt.u32.u64 %0, t; }" : "=r"(a) : "l"(p));
    return a;
}
__device__ __forceinline__ void cpa16(uint32_t d, const void* s){
    asm volatile("cp.async.cg.shared.global [%0], [%1], 16;" :: "r"(d), "l"(s));
}
__device__ __forceinline__ void cpa_commit(){ asm volatile("cp.async.commit_group;" ::: "memory"); }
__device__ __forceinline__ void cpa_wait0(){ asm volatile("cp.async.wait_group 0;" ::: "memory"); }
__device__ __forceinline__ void cpa_wait1(){ asm volatile("cp.async.wait_group 1;" ::: "memory"); }
__device__ __forceinline__ void ldsm4(uint32_t* r, uint32_t a){
    asm volatile("ldmatrix.sync.aligned.m8n8.x4.shared.b16 {%0,%1,%2,%3}, [%4];"
        : "=r"(r[0]), "=r"(r[1]), "=r"(r[2]), "=r"(r[3]) : "r"(a));
}
__device__ __forceinline__ void mma16816(float* d, const uint32_t* a, const uint32_t* b){
    asm volatile(
        "mma.sync.aligned.m16n8k16.row.col.f32.f16.f16.f32 "
        "{%0,%1,%2,%3}, {%4,%5,%6,%7}, {%8,%9}, {%0,%1,%2,%3};"
        : "+f"(d[0]), "+f"(d[1]), "+f"(d[2]), "+f"(d[3])
        : "r"(a[0]), "r"(a[1]), "r"(a[2]), "r"(a[3]), "r"(b[0]), "r"(b[1]));
}
__device__ __forceinline__ uint32_t packh2(float x, float y){
    __half2 p; p.x = __float2half_rn(x); p.y = __float2half_rn(y);
    return *(uint32_t*)&p;
}

// stage one [128 rows][64 k] fp16 tile, SW128 swizzle, cp.async — 256 threads, 4x16B each
__device__ __forceinline__ void stage_tile(uint32_t smA, const __half* g, int ld,
                                           int row0, int k0, int tid)
{
    int r = tid >> 1, s0 = (tid & 1) * 4;
    const __half* src = g + (long long)(row0 + r) * ld + k0 + s0 * 8;
    uint32_t offb = (uint32_t)(r * 128 + s0 * 16);
    #pragma unroll
    for (int j = 0; j < 4; j++){
        uint32_t off = offb + j * 16;
        uint32_t sw = off ^ ((off >> 3) & 0x70u);
        cpa16(smA + sw, src + j * 8);
    }
}
// [64 rows][64 k] tile with 256 threads, 2x16B each
__device__ __forceinline__ void stage_tile64(uint32_t smA, const __half* g, int ld,
                                             int row0, int k0, int tid)
{
    int r = tid >> 2, s0 = (tid & 3) * 2;
    const __half* src = g + (long long)(row0 + r) * ld + k0 + s0 * 8;
    uint32_t offb = (uint32_t)(r * 128 + s0 * 16);
    #pragma unroll
    for (int j = 0; j < 2; j++){
        uint32_t off = offb + j * 16;
        uint32_t sw = off ^ ((off >> 3) & 0x70u);
        cpa16(smA + sw, src + j * 8);
    }
}

struct OutD {
    float* f;
    __half* h;
    const float* rowscale;
    float factor;
    int ldc;
    int colsub;
    int relu;
    int vtrans;
    long long sC;
};

#define GSTG 24576                 // A 16KB + B 8KB
#define SMEM_GEMM (2*GSTG)         // 49152
#define SMEM_FLASH 196608          // Q 64KB + K 64KB + V 2x32KB

// ================= dense GEMM: 256 threads, 8 warps (4x2), block 128x64, 2-stage =================
__global__ __launch_bounds__(256, 2)
void bf_gemm(const __half* __restrict__ A1, int lda1, int K1,
             const __half* __restrict__ A2, int lda2, int Ktot,
             const __half* __restrict__ B, int ldb,
             const float* __restrict__ bias, long long sA1, long long sB,
             int split, OutD o0, OutD o1)
{
    extern __shared__ __align__(1024) char smraw[];
    const uint32_t smb = smem_u32(smraw);
    const int tid = threadIdx.x, wid = tid >> 5, lane = tid & 31;
    const int wm = wid >> 1, wn = wid & 1;
    const int row0 = blockIdx.y * 128, col0 = blockIdx.x * 64;
    const int z = blockIdx.z;
    A1 += (long long)z * sA1;
    B  += (long long)z * sB;

    const int arow = ((lane >> 3) & 1) * 8 + (lane & 7);
    const int ak8  = ((lane >> 4) & 1) * 8;
    const int brow = ((lane >> 4) & 1) * 8 + (lane & 7);
    const int bk8  = ((lane >> 3) & 1) * 8;

    float acc[2][4][4];
    #pragma unroll
    for (int i = 0; i < 2; i++)
        #pragma unroll
        for (int j = 0; j < 4; j++)
            #pragma unroll
            for (int k = 0; k < 4; k++) acc[i][j][k] = 0.f;

    const int T = Ktot / 64;
    auto do_stage = [&](int t, int buf){
        int k0 = t * 64;
        const __half* a; int ld, ka;
        if (k0 < K1){ a = A1; ld = lda1; ka = k0; }
        else        { a = A2; ld = lda2; ka = k0 - K1; }
        uint32_t sb = smb + buf * GSTG;
        stage_tile(sb + 0,      a, ld,  row0, ka, tid);
        stage_tile64(sb + 16384, B, ldb, col0, k0, tid);
        cpa_commit();
    };

    do_stage(0, 0);
    for (int t = 0; t < T; t++){
        if (t + 1 < T){ do_stage(t + 1, (t + 1) & 1); cpa_wait1(); }
        else          { cpa_wait0(); }
        __syncthreads();
        uint32_t sm = smb + (t & 1) * GSTG;
        #pragma unroll
        for (int ks = 0; ks < 4; ks++){
            const int kk = ks * 16;
            uint32_t ah[2][4], bh[4][2], t4[4];
            #pragma unroll
            for (int mt = 0; mt < 2; mt++){
                uint32_t off = (uint32_t)((wm*32 + mt*16 + arow) * 128 + (kk + ak8) * 2);
                uint32_t sw = off ^ ((off >> 3) & 0x70u);
                ldsm4(ah[mt], sm + sw);
            }
            #pragma unroll
            for (int np = 0; np < 2; np++){
                uint32_t off = (uint32_t)((wn*32 + np*16 + brow) * 128 + (kk + bk8) * 2);
                uint32_t sw = off ^ ((off >> 3) & 0x70u);
                ldsm4(t4, sm + 16384 + sw);
                bh[np*2][0]=t4[0]; bh[np*2][1]=t4[1]; bh[np*2+1][0]=t4[2]; bh[np*2+1][1]=t4[3];
            }
            #pragma unroll
            for (int mt = 0; mt < 2; mt++)
                #pragma unroll
                for (int nt = 0; nt < 4; nt++)
                    mma16816(acc[mt][nt], ah[mt], bh[nt]);
        }
        __syncthreads();
    }

    const OutD& od = (blockIdx.x < split) ? o0 : o1;
    const int lq = lane >> 2, le = (lane & 3) * 2;
    #pragma unroll
    for (int mt = 0; mt < 2; mt++){
        int gr0 = row0 + wm*32 + mt*16 + lq;
        float rs0 = od.rowscale ? od.rowscale[gr0]   * od.factor : od.factor;
        float rs1 = od.rowscale ? od.rowscale[gr0+8] * od.factor : od.factor;
        #pragma unroll
        for (int nt = 0; nt < 4; nt++){
            int gc = col0 + wn*32 + nt*8 + le;
            float b0 = bias ? bias[gc] : 0.f, b1 = bias ? bias[gc+1] : 0.f;
            float v00 = (acc[mt][nt][0] + b0) * rs0, v01 = (acc[mt][nt][1] + b1) * rs0;
            float v10 = (acc[mt][nt][2] + b0) * rs1, v11 = (acc[mt][nt][3] + b1) * rs1;
            if (od.relu){
                v00 = fmaxf(v00, 0.f); v01 = fmaxf(v01, 0.f);
                v10 = fmaxf(v10, 0.f); v11 = fmaxf(v11, 0.f);
            }
            if (od.vtrans){
                int d = gc - od.colsub;
                int bidx = gr0 >> 9, kt0 = gr0 & 511;
                long long o00 = ((long long)bidx * MSG + d) * NAG + kt0;
                od.h[o00]           = __float2half_rn(v00);
                od.h[o00 + NAG]     = __float2half_rn(v01);
                od.h[o00 + 8]       = __float2half_rn(v10);
                od.h[o00 + NAG + 8] = __float2half_rn(v11);
                continue;
            }
            long long i0 = od.sC * z + (long long)gr0 * od.ldc + (gc - od.colsub);
            long long i1 = od.sC * z + (long long)(gr0 + 8) * od.ldc + (gc - od.colsub);
            if (od.f){
                *(float2*)(od.f + i0) = make_float2(v00, v01);
                *(float2*)(od.f + i1) = make_float2(v10, v11);
            }
            if (od.h){
                *(uint32_t*)(od.h + i0) = packh2(v00, v01);
                *(uint32_t*)(od.h + i1) = packh2(v10, v11);
            }
        }
    }
}

// ================= flash: Qext resident in smem, single-K + double-V buffers =================
// smem: [0,64K) Qext (4 segs of 16KB), [64K,128K) Kext, [128K,192K) V x2
__global__ __launch_bounds__(256, 1)
void flash_kernel(const __half* __restrict__ Qe,   // [ROWS][256]
                  const __half* __restrict__ Ke,   // [ROWS][256]
                  const __half* __restrict__ V,    // [b][128 d][512 k]
                  __half* __restrict__ agg)
{
    extern __shared__ __align__(1024) char smraw[];
    const uint32_t smQ = smem_u32(smraw);
    const uint32_t smK = smQ + 65536;
    const uint32_t smV = smQ + 131072;
    const int tid = threadIdx.x, w = tid >> 5, lane = tid & 31;
    const int q0 = blockIdx.x * 128;
    const int b = blockIdx.y;
    const int gr = b * NAG;
    const long long vbase = (long long)b * MSG * NAG;

    const int arow = ((lane >> 3) & 1) * 8 + (lane & 7);
    const int ak8  = ((lane >> 4) & 1) * 8;
    const int brow = ((lane >> 4) & 1) * 8 + (lane & 7);
    const int bk8  = ((lane >> 3) & 1) * 8;
    const int lq = lane >> 2;

    // prologue: Q (4 segs) + K(0) (4 segs) + V(0) — one group
    #pragma unroll
    for (int s = 0; s < 4; s++) stage_tile(smQ + s*16384, Qe, 256, gr + q0, s*64, tid);
    #pragma unroll
    for (int s = 0; s < 4; s++) stage_tile(smK + s*16384, Ke, 256, gr + 0, s*64, tid);
    stage_tile(smV + 0,     V + vbase, NAG, 0, 0,  tid);
    stage_tile(smV + 16384, V + vbase, NAG, 0, 64, tid);
    cpa_commit();

    float O[16][4];
    #pragma unroll
    for (int nt = 0; nt < 16; nt++)
        #pragma unroll
        for (int j = 0; j < 4; j++) O[nt][j] = 0.f;
    float m0 = -1e30f, m1 = -1e30f, sum0 = 0.f, sum1 = 0.f;

    for (int kt = 0; kt < 4; kt++){
        // prefetch V(kt+1) into other V buffer (free since kt-1's PV)
        if (kt + 1 < 4){
            uint32_t vb = smV + ((kt+1)&1) * 32768;
            stage_tile(vb + 0,     V + vbase, NAG, 0, (kt+1)*128,      tid);
            stage_tile(vb + 16384, V + vbase, NAG, 0, (kt+1)*128 + 64, tid);
            cpa_commit();
            cpa_wait1();     // current kt's K,V done
        } else {
            cpa_wait0();
        }
        __syncthreads();

        // ---- S = Qext · Kext^T : 16 uninterrupted feature chunks ----
        float S[16][4];
        #pragma unroll
        for (int nt = 0; nt < 16; nt++)
            #pragma unroll
            for (int j = 0; j < 4; j++) S[nt][j] = 0.f;

        #pragma unroll
        for (int c = 0; c < 16; c++){
            const int seg = c >> 2, kk = (c & 3) * 16;
            uint32_t aq[4], t4[4];
            {
                uint32_t off = (uint32_t)((w*16 + arow) * 128 + (kk + ak8) * 2);
                uint32_t sw = off ^ ((off >> 3) & 0x70u);
                ldsm4(aq, smQ + seg*16384 + sw);
            }
            #pragma unroll
            for (int np = 0; np < 8; np++){
                uint32_t off = (uint32_t)((np*16 + brow) * 128 + (kk + bk8) * 2);
                uint32_t sw = off ^ ((off >> 3) & 0x70u);
                ldsm4(t4, smK + seg*16384 + sw);
                uint32_t b0[2] = {t4[0], t4[1]}, b1[2] = {t4[2], t4[3]};
                mma16816(S[np*2],   aq, b0);
                mma16816(S[np*2+1], aq, b1);
            }
        }
        __syncthreads();   // all warps done with smK before restaging

        // stage K(kt+1) into the (single) K buffer; hidden under softmax+PV
        if (kt + 1 < 4){
            #pragma unroll
            for (int s = 0; s < 4; s++)
                stage_tile(smK + s*16384, Ke, 256, gr + (kt+1)*128, s*64, tid);
            cpa_commit();
        }

        // ---- online softmax ----
        float mx0 = -1e30f, mx1 = -1e30f;
        #pragma unroll
        for (int nt = 0; nt < 16; nt++){
            mx0 = fmaxf(mx0, fmaxf(S[nt][0], S[nt][1]));
            mx1 = fmaxf(mx1, fmaxf(S[nt][2], S[nt][3]));
        }
        mx0 = fmaxf(mx0, __shfl_xor_sync(0xffffffffu, mx0, 1));
        mx0 = fmaxf(mx0, __shfl_xor_sync(0xffffffffu, mx0, 2));
        mx1 = fmaxf(mx1, __shfl_xor_sync(0xffffffffu, mx1, 1));
        mx1 = fmaxf(mx1, __shfl_xor_sync(0xffffffffu, mx1, 2));
        float M0 = fmaxf(m0, mx0), M1 = fmaxf(m1, mx1);
        float f0 = __expf(m0 - M0), f1 = __expf(m1 - M1);
        float rs0 = 0.f, rs1 = 0.f;
        #pragma unroll
        for (int nt = 0; nt < 16; nt++){
            float p0 = __expf(S[nt][0] - M0); S[nt][0] = p0; rs0 += p0;
            float p1 = __expf(S[nt][1] - M0); S[nt][1] = p1; rs0 += p1;
            float p2 = __expf(S[nt][2] - M1); S[nt][2] = p2; rs1 += p2;
            float p3 = __expf(S[nt][3] - M1); S[nt][3] = p3; rs1 += p3;
        }
        rs0 += __shfl_xor_sync(0xffffffffu, rs0, 1);
        rs0 += __shfl_xor_sync(0xffffffffu, rs0, 2);
        rs1 += __shfl_xor_sync(0xffffffffu, rs1, 1);
        rs1 += __shfl_xor_sync(0xffffffffu, rs1, 2);
        sum0 = sum0 * f0 + rs0;
        sum1 = sum1 * f1 + rs1;
        m0 = M0; m1 = M1;
        #pragma unroll
        for (int nt = 0; nt < 16; nt++){
            O[nt][0] *= f0; O[nt][1] *= f0; O[nt][2] *= f1; O[nt][3] *= f1;
        }

        // ---- P·V (V resident; no sync needed after: V buffer not reused until kt+2) ----
        uint32_t vb = smV + (kt & 1) * 32768;
        #pragma unroll
        for (int ks = 0; ks < 8; ks++){
            uint32_t ap[4];
            ap[0] = packh2(S[2*ks][0],   S[2*ks][1]);
            ap[1] = packh2(S[2*ks][2],   S[2*ks][3]);
            ap[2] = packh2(S[2*ks+1][0], S[2*ks+1][1]);
            ap[3] = packh2(S[2*ks+1][2], S[2*ks+1][3]);
            uint32_t base = (ks < 4) ? vb : vb + 16384;
            const int kk = (ks & 3) * 16;
            #pragma unroll
            for (int np = 0; np < 8; np++){
                uint32_t off = (uint32_t)((np*16 + brow) * 128 + (kk + bk8) * 2);
                uint32_t sw = off ^ ((off >> 3) & 0x70u);
                uint32_t t4[4];
                ldsm4(t4, base + sw);
                uint32_t b0[2] = {t4[0], t4[1]}, b1[2] = {t4[2], t4[3]};
                mma16816(O[np*2],   ap, b0);
                mma16816(O[np*2+1], ap, b1);
            }
        }
        __syncthreads();   // V buffer (kt&1) free for restage at kt+1 top
    }

    float inv0 = 1.f / sum0, inv1 = 1.f / sum1;
    long long r0 = (long long)(gr + q0 + w*16 + lq) * MSG;
    long long r1 = r0 + 8 * MSG;
    #pragma unroll
    for (int nt = 0; nt < 16; nt++){
        int d = nt*8 + (lane & 3)*2;
        *(uint32_t*)(agg + r0 + d) = packh2(O[nt][0] * inv0, O[nt][1] * inv0);
        *(uint32_t*)(agg + r1 + d) = packh2(O[nt][2] * inv1, O[nt][3] * inv1);
    }
}

// ---------------- packing kernels ----------------
__global__ void pack_obs(const float* __restrict__ obs, __half* __restrict__ h)
{
    long long i = (long long)blockIdx.x * 256 + threadIdx.x;
    h[i] = __float2half_rn(obs[i]);
}
__global__ void pack_we(const float* __restrict__ We, __half* __restrict__ hi)
{
    int i = blockIdx.x * 256 + threadIdx.x;
    int n = i >> 7, k = i & 127;
    hi[i] = __float2half_rn(We[k*256 + n]);
}
__global__ void pack_wcat(const float* __restrict__ Wc, const float* __restrict__ Wn,
                          const float* __restrict__ Wb, const float* __restrict__ Wq,
                          const float* __restrict__ bc, const float* __restrict__ bn,
                          const float* __restrict__ bbp, const float* __restrict__ bq,
                          __half* __restrict__ hi, float* __restrict__ bcat)
{
    int i = blockIdx.x * 256 + threadIdx.x;
    int n = i >> 8, k = i & 255;
    float v;
    if (n < 32)       v = Wc[k*32 + n];
    else if (n < 96)  v = Wn[k*64 + (n-32)];
    else if (n < 128) v = Wb[k*32 + (n-96)];
    else              v = Wq[k*128 + (n-128)];
    hi[i] = __float2half_rn(v);
    if (k == 0)
        bcat[n] = (n < 32) ? bc[n] : (n < 96) ? bn[n-32] : (n < 128) ? bbp[n-96] : bq[n-128];
}
__global__ void pack_wkv(const float* __restrict__ Wk, const float* __restrict__ Wv,
                         const float* __restrict__ bk, const float* __restrict__ bv,
                         __half* __restrict__ hi, float* __restrict__ bkv)
{
    int i = blockIdx.x * 256 + threadIdx.x;
    int n = i >> 7, k = i & 127;
    float v = (n < 128) ? Wk[k*128 + n] : Wv[k*128 + (n-128)];
    hi[i] = __float2half_rn(v);
    if (k == 0) bkv[n] = (n < 128) ? bk[n] : bv[n-128];
}
__global__ void pack_wp(const float* __restrict__ Wp, __half* __restrict__ hi)
{
    int i = blockIdx.x * 256 + threadIdx.x;
    int n = i / 384, k = i % 384;
    hi[i] = __float2half_rn(Wp[k*256 + n]);
}

// ---------------- importance + norm; writes obs_scaled into qext & kext cols 128-255 ----------------
__global__ void impnorm_kernel(const __half* __restrict__ enc,
                               const float* __restrict__ obs,
                               const float* __restrict__ Wi,
                               const float* __restrict__ bi,
                               float* __restrict__ imp,
                               __half* __restrict__ qext,
                               __half* __restrict__ kext)
{
    int row = blockIdx.x * 8 + threadIdx.y;
    int lane = threadIdx.x;
    const __half* e = enc + (long long)row * HID;
    const float* o = obs + (long long)row * OBS;
    float d = 0.f, ss = 0.f;
    float ov[4];
    #pragma unroll
    for (int i = 0; i < HID/32; i++){
        int k = lane + 32*i;
        d += __half2float(e[k]) * Wi[k];
    }
    #pragma unroll
    for (int i = 0; i < OBS/32; i++){ ov[i] = o[lane + 32*i]; ss += ov[i]*ov[i]; }
    #pragma unroll
    for (int off = 16; off; off >>= 1){
        d  += __shfl_xor_sync(0xffffffffu, d, off);
        ss += __shfl_xor_sync(0xffffffffu, ss, off);
    }
    if (lane == 0)
        imp[row] = 1.f / (1.f + expf(-(d + bi[0])));
    float s = 0.7071067811865476f / (sqrtf(ss) + 1e-8f);
    #pragma unroll
    for (int i = 0; i < OBS/32; i++){
        int k = lane + 32*i;
        __half v = __float2half_rn(ov[i] * s);
        qext[(long long)row * 256 + 128 + k] = v;
        kext[(long long)row * 256 + 128 + k] = v;
    }
}

// ---------------- head ----------------
__global__ void head_kernel(const float* __restrict__ x,
                            const float* __restrict__ Wa,
                            const float* __restrict__ ba,
                            const float* __restrict__ Wcr,
                            const float* __restrict__ bcr,
                            float* __restrict__ out)
{
    int row = blockIdx.x * 8 + threadIdx.y;
    int lane = threadIdx.x;
    const float* xr = x + (long long)row * HID;
    float xv[8];
    #pragma unroll
    for (int i = 0; i < 8; i++) xv[i] = xr[lane + 32*i];
    #pragma unroll
    for (int j = 0; j < 17; j++){
        float p = 0.f;
        #pragma unroll
        for (int i = 0; i < 8; i++){
            int k = lane + 32*i;
            float w = (j < 16) ? Wa[(long long)k * NACT + j] : Wcr[k];
            p += xv[i] * w;
        }
        #pragma unroll
        for (int off = 16; off; off >>= 1) p += __shfl_down_sync(0xffffffffu, p, off);
        if (lane == 0){
            if (j < 16) out[(long long)row * NACT + j] = p + ba[j];
            else        out[(long long)ROWS * NACT + row] = p + bcr[0];
        }
    }
}

// ---------------- launch ----------------
extern "C" void kernel_launch(void* const* d_in, const int* in_sizes, int n_in,
                              void* d_out, int out_size)
{
    const float* obs = (const float*)d_in[0];
    const float* We  = (const float*)d_in[2];   const float* be  = (const float*)d_in[3];
    const float* Wc  = (const float*)d_in[4];   const float* bc  = (const float*)d_in[5];
    const float* Wn  = (const float*)d_in[6];   const float* bn  = (const float*)d_in[7];
    const float* Wb  = (const float*)d_in[8];   const float* bbp = (const float*)d_in[9];
    const float* Wi  = (const float*)d_in[10];  const float* bi  = (const float*)d_in[11];
    const float* Wq  = (const float*)d_in[12];  const float* bq  = (const float*)d_in[13];
    const float* Wk  = (const float*)d_in[14];  const float* bk  = (const float*)d_in[15];
    const float* Wv  = (const float*)d_in[16];  const float* bv  = (const float*)d_in[17];
    const float* Wp  = (const float*)d_in[18];  const float* bp  = (const float*)d_in[19];
    const float* Wa  = (const float*)d_in[20];  const float* ba  = (const float*)d_in[21];
    const float* Wcr = (const float*)d_in[22];  const float* bcr = (const float*)d_in[23];
    float* out = (float*)d_out;

    #define GA(p, sym) cudaGetSymbolAddress((void**)&p, sym)
    __half *enc,*msgq,*qext,*kext,*obh,*vt,*agg,*WeT,*WcT,*WkvT,*WpT;
    float *imp,*xb,*bcat,*bkv;
    GA(enc,g_enc); GA(msgq,g_msgq); GA(qext,g_qext); GA(kext,g_kext); GA(obh,g_obs);
    GA(vt,g_vT); GA(agg,g_agg); GA(imp,g_imp); GA(xb,g_x);
    GA(bcat,g_bcat); GA(bkv,g_bkv);
    GA(WeT,g_WeT); GA(WcT,g_WcatT); GA(WkvT,g_WkvT); GA(WpT,g_WpT);
    #undef GA

    cudaFuncSetAttribute(bf_gemm,      cudaFuncAttributeMaxDynamicSharedMemorySize, SMEM_GEMM);
    cudaFuncSetAttribute(flash_kernel, cudaFuncAttributeMaxDynamicSharedMemorySize, SMEM_FLASH);

    OutD z = {};

    // packs
    pack_obs <<<ROWS*OBS/256, 256>>>(obs, obh);
    pack_we  <<<128, 256>>>(We, WeT);
    pack_wcat<<<256, 256>>>(Wc, Wn, Wb, Wq, bc, bn, bbp, bq, WcT, bcat);

    // enc = relu(obs @ We + be) -> fp16
    {
        OutD o = z; o.h = enc; o.factor = 1.f; o.ldc = 256; o.relu = 1;
        bf_gemm<<<dim3(4,256,1), 256, SMEM_GEMM>>>(obh, OBS, OBS, nullptr, 0, OBS,
                                                   WeT, OBS, be, 0, 0, 4, o, o);
    }
    // imp + obs_scaled into qext/kext halves
    impnorm_kernel<<<ROWS/8, dim3(32,8)>>>(enc, obs, Wi, bi, imp, qext, kext);
    // msgq cols 0-127 -> msg; cols 128-255 (Q) scaled by imp/sqrt(128) -> qext cols 0-127
    {
        OutD o0 = z; o0.h = msgq; o0.factor = 1.f; o0.ldc = 256;
        OutD o1 = z; o1.h = qext; o1.rowscale = imp; o1.factor = 0.08838834764831845f;
        o1.ldc = 256; o1.colsub = 128;
        bf_gemm<<<dim3(4,256,1), 256, SMEM_GEMM>>>(enc, 256, 256, nullptr, 0, 256,
                                                   WcT, 256, bcat, 0, 0, 2, o0, o1);
    }
    // pack KV weights
    pack_wkv <<<128, 256>>>(Wk, Wv, bk, bv, WkvT, bkv);
    // kv: K scaled by imp -> kext cols 0-127; V -> transposed vT
    {
        OutD o0 = z; o0.h = kext; o0.rowscale = imp; o0.factor = 1.f; o0.ldc = 256;
        OutD o1 = z; o1.h = vt; o1.factor = 1.f; o1.colsub = 128; o1.vtrans = 1;
        bf_gemm<<<dim3(4,256,1), 256, SMEM_GEMM>>>(msgq, 256, 128, nullptr, 0, 128,
                                                   WkvT, 128, bkv, 0, 0, 2, o0, o1);
    }
    // pack Wp
    pack_wp  <<<384, 256>>>(Wp, WpT);
    // flash attention -> agg fp16
    flash_kernel<<<dim3(4, BSZ), 256, SMEM_FLASH>>>(qext, kext, vt, agg);
    // x = relu([enc|agg] @ Wp + bp) -> fp32
    {
        OutD o = z; o.f = xb; o.factor = 1.f; o.ldc = 256; o.relu = 1;
        bf_gemm<<<dim3(4,256,1), 256, SMEM_GEMM>>>(enc, 256, 256, agg, 128, 384,
                                                   WpT, 384, bp, 0, 0, 4, o, o);
    }
    // heads
    head_kernel<<<ROWS/8, dim3(32,8)>>>(xb, Wa, ba, Wcr, bcr, out);
}

// round 17
// speedup vs baseline: 1.0400x; 1.0400x over previous
#include <cuda_runtime.h>
#include <cuda_fp16.h>
#include <stdint.h>
#include <math.h>

#define BSZ 64
#define NAG 512
#define OBS 128
#define HID 256
#define MSG 128
#define NACT 16
#define ROWS (BSZ*NAG)   // 32768

// ---------------- scratch (device globals, fp16) ----------------
__device__ __align__(16) __half g_enc[(size_t)ROWS*HID];
__device__ __align__(16) __half g_msgq[(size_t)ROWS*256];   // 0-127 msg, 128-255 Q(scaled)
__device__ __align__(16) __half g_ks[(size_t)ROWS*MSG];     // K scaled by imp
__device__ __align__(16) __half g_obs[(size_t)ROWS*OBS];
__device__ __align__(16) __half g_obss[(size_t)ROWS*OBS];   // scaled sqrt(.5)/nrm
__device__ float g_imp[ROWS];
__device__ __align__(16) __half g_vT[(size_t)BSZ*MSG*NAG];  // [b][d][k]
__device__ __align__(16) __half g_agg[(size_t)ROWS*MSG];
__device__ float g_x[(size_t)ROWS*HID];
__device__ float g_bcat[256];
__device__ float g_bkv[256];
__device__ __align__(16) __half g_WeT[256*128];
__device__ __align__(16) __half g_WcatT[256*256];
__device__ __align__(16) __half g_WkvT[256*128];
__device__ __align__(16) __half g_WpT[256*384];

// ---------------- helpers ----------------
__device__ __forceinline__ uint32_t smem_u32(const void* p){
    uint32_t a;
    asm("{ .reg .u64 t; cvta.to.shared.u64 t, %1; cvt.u32.u64 %0, t; }" : "=r"(a) : "l"(p));
    return a;
}
__device__ __forceinline__ void cpa16(uint32_t d, const void* s){
    asm volatile("cp.async.cg.shared.global [%0], [%1], 16;" :: "r"(d), "l"(s));
}
__device__ __forceinline__ void cpa_commit(){ asm volatile("cp.async.commit_group;" ::: "memory"); }
__device__ __forceinline__ void cpa_wait0(){ asm volatile("cp.async.wait_group 0;" ::: "memory"); }
__device__ __forceinline__ void cpa_wait1(){ asm volatile("cp.async.wait_group 1;" ::: "memory"); }
__device__ __forceinline__ void cpa_wait2(){ asm volatile("cp.async.wait_group 2;" ::: "memory"); }
__device__ __forceinline__ void ldsm4(uint32_t* r, uint32_t a){
    asm volatile("ldmatrix.sync.aligned.m8n8.x4.shared.b16 {%0,%1,%2,%3}, [%4];"
        : "=r"(r[0]), "=r"(r[1]), "=r"(r[2]), "=r"(r[3]) : "r"(a));
}
__device__ __forceinline__ void mma16816(float* d, const uint32_t* a, const uint32_t* b){
    asm volatile(
        "mma.sync.aligned.m16n8k16.row.col.f32.f16.f16.f32 "
        "{%0,%1,%2,%3}, {%4,%5,%6,%7}, {%8,%9}, {%0,%1,%2,%3};"
        : "+f"(d[0]), "+f"(d[1]), "+f"(d[2]), "+f"(d[3])
        : "r"(a[0]), "r"(a[1]), "r"(a[2]), "r"(a[3]), "r"(b[0]), "r"(b[1]));
}
__device__ __forceinline__ uint32_t packh2(float x, float y){
    __half2 p; p.x = __float2half_rn(x); p.y = __float2half_rn(y);
    return *(uint32_t*)&p;
}

// stage [128 rows][64 k] tile, SW128, 256 threads, 4x16B each
__device__ __forceinline__ void stage_tile(uint32_t smA, const __half* g, int ld,
                                           int row0, int k0, int tid)
{
    int r = tid >> 1, s0 = (tid & 1) * 4;
    const __half* src = g + (long long)(row0 + r) * ld + k0 + s0 * 8;
    uint32_t offb = (uint32_t)(r * 128 + s0 * 16);
    #pragma unroll
    for (int j = 0; j < 4; j++){
        uint32_t off = offb + j * 16;
        uint32_t sw = off ^ ((off >> 3) & 0x70u);
        cpa16(smA + sw, src + j * 8);
    }
}
// stage [128 rows][64 k] tile, 512 threads, 2x16B each
__device__ __forceinline__ void stageA512(uint32_t smA, const __half* g, int ld,
                                          int row0, int k0, int tid)
{
    int r = tid >> 2, s0 = (tid & 3) * 2;
    const __half* src = g + (long long)(row0 + r) * ld + k0 + s0 * 8;
    uint32_t offb = (uint32_t)(r * 128 + s0 * 16);
    #pragma unroll
    for (int j = 0; j < 2; j++){
        uint32_t off = offb + j * 16;
        uint32_t sw = off ^ ((off >> 3) & 0x70u);
        cpa16(smA + sw, src + j * 8);
    }
}
// stage [64 rows][64 k] tile, 512 threads, 1x16B each
__device__ __forceinline__ void stageB512(uint32_t smA, const __half* g, int ld,
                                          int row0, int k0, int tid)
{
    int r = tid >> 3, s0 = tid & 7;
    const __half* src = g + (long long)(row0 + r) * ld + k0 + s0 * 8;
    uint32_t off = (uint32_t)(r * 128 + s0 * 16);
    uint32_t sw = off ^ ((off >> 3) & 0x70u);
    cpa16(smA + sw, src);
}

struct OutD {
    float* f;
    __half* h;
    const float* rowscale;
    float factor;
    int ldc;
    int colsub;
    int relu;
    int vtrans;
    long long sC;
};

#define GSTG 24576                 // A 16KB + B 8KB
#define SMEM_GEMM (2*GSTG)         // 49152 -> 2 CTAs/SM (regs <= 64)
#define SMEM_FLASH 98304           // 2 S-stages (64KB) + V (32KB)

// ================= dense GEMM: 512 threads, 16 warps (4x4), warp 32x16, block 128x64, 2-stage =================
__global__ __launch_bounds__(512, 2)
void bf_gemm(const __half* __restrict__ A1, int lda1, int K1,
             const __half* __restrict__ A2, int lda2, int Ktot,
             const __half* __restrict__ B, int ldb,
             const float* __restrict__ bias, long long sA1, long long sB,
             int split, OutD o0, OutD o1)
{
    extern __shared__ __align__(1024) char smraw[];
    const uint32_t smb = smem_u32(smraw);
    const int tid = threadIdx.x, wid = tid >> 5, lane = tid & 31;
    const int wm = wid >> 2, wn = wid & 3;
    const int row0 = blockIdx.y * 128, col0 = blockIdx.x * 64;
    const int z = blockIdx.z;
    A1 += (long long)z * sA1;
    B  += (long long)z * sB;

    const int arow = ((lane >> 3) & 1) * 8 + (lane & 7);
    const int ak8  = ((lane >> 4) & 1) * 8;
    const int brow = ((lane >> 4) & 1) * 8 + (lane & 7);
    const int bk8  = ((lane >> 3) & 1) * 8;

    float acc[2][2][4];
    #pragma unroll
    for (int i = 0; i < 2; i++)
        #pragma unroll
        for (int j = 0; j < 2; j++)
            #pragma unroll
            for (int k = 0; k < 4; k++) acc[i][j][k] = 0.f;

    const int T = Ktot / 64;
    auto do_stage = [&](int t, int buf){
        int k0 = t * 64;
        const __half* a; int ld, ka;
        if (k0 < K1){ a = A1; ld = lda1; ka = k0; }
        else        { a = A2; ld = lda2; ka = k0 - K1; }
        uint32_t sb = smb + buf * GSTG;
        stageA512(sb + 0,      a, ld,  row0, ka, tid);
        stageB512(sb + 16384,  B, ldb, col0, k0, tid);
        cpa_commit();
    };

    do_stage(0, 0);
    for (int t = 0; t < T; t++){
        if (t + 1 < T){ do_stage(t + 1, (t + 1) & 1); cpa_wait1(); }
        else          { cpa_wait0(); }
        __syncthreads();
        uint32_t sm = smb + (t & 1) * GSTG;
        #pragma unroll
        for (int ks = 0; ks < 4; ks++){
            const int kk = ks * 16;
            uint32_t ah[2][4], t4[4];
            #pragma unroll
            for (int mt = 0; mt < 2; mt++){
                uint32_t off = (uint32_t)((wm*32 + mt*16 + arow) * 128 + (kk + ak8) * 2);
                uint32_t sw = off ^ ((off >> 3) & 0x70u);
                ldsm4(ah[mt], sm + sw);
            }
            {
                uint32_t off = (uint32_t)((wn*16 + brow) * 128 + (kk + bk8) * 2);
                uint32_t sw = off ^ ((off >> 3) & 0x70u);
                ldsm4(t4, sm + 16384 + sw);
            }
            uint32_t b0[2] = {t4[0], t4[1]}, b1[2] = {t4[2], t4[3]};
            #pragma unroll
            for (int mt = 0; mt < 2; mt++){
                mma16816(acc[mt][0], ah[mt], b0);
                mma16816(acc[mt][1], ah[mt], b1);
            }
        }
        __syncthreads();
    }

    const OutD& od = (blockIdx.x < split) ? o0 : o1;
    const int lq = lane >> 2, le = (lane & 3) * 2;
    #pragma unroll
    for (int mt = 0; mt < 2; mt++){
        int gr0 = row0 + wm*32 + mt*16 + lq;
        float rs0 = od.rowscale ? od.rowscale[gr0]   * od.factor : od.factor;
        float rs1 = od.rowscale ? od.rowscale[gr0+8] * od.factor : od.factor;
        #pragma unroll
        for (int nt = 0; nt < 2; nt++){
            int gc = col0 + wn*16 + nt*8 + le;
            float b0 = bias ? bias[gc] : 0.f, b1 = bias ? bias[gc+1] : 0.f;
            float v00 = (acc[mt][nt][0] + b0) * rs0, v01 = (acc[mt][nt][1] + b1) * rs0;
            float v10 = (acc[mt][nt][2] + b0) * rs1, v11 = (acc[mt][nt][3] + b1) * rs1;
            if (od.relu){
                v00 = fmaxf(v00, 0.f); v01 = fmaxf(v01, 0.f);
                v10 = fmaxf(v10, 0.f); v11 = fmaxf(v11, 0.f);
            }
            if (od.vtrans){
                int d = gc - od.colsub;
                int bidx = gr0 >> 9, kt0 = gr0 & 511;
                long long o00 = ((long long)bidx * MSG + d) * NAG + kt0;
                od.h[o00]           = __float2half_rn(v00);
                od.h[o00 + NAG]     = __float2half_rn(v01);
                od.h[o00 + 8]       = __float2half_rn(v10);
                od.h[o00 + NAG + 8] = __float2half_rn(v11);
                continue;
            }
            long long i0 = od.sC * z + (long long)gr0 * od.ldc + (gc - od.colsub);
            long long i1 = od.sC * z + (long long)(gr0 + 8) * od.ldc + (gc - od.colsub);
            if (od.f){
                *(float2*)(od.f + i0) = make_float2(v00, v01);
                *(float2*)(od.f + i1) = make_float2(v10, v11);
            }
            if (od.h){
                *(uint32_t*)(od.h + i0) = packh2(v00, v01);
                *(uint32_t*)(od.h + i1) = packh2(v10, v11);
            }
        }
    }
}

// ================= flash attention (R12 version): 256 threads, V prefetched under S =================
__global__ __launch_bounds__(256, 1)
void flash_kernel(const __half* __restrict__ Q,   // +128 offset, ld 256
                  const __half* __restrict__ K,   // ld 128
                  const __half* __restrict__ Ob,  // obs scaled, ld 128
                  const __half* __restrict__ V,   // [b][128 d][512 k]
                  __half* __restrict__ agg)
{
    extern __shared__ __align__(1024) char smraw[];
    const uint32_t smb = smem_u32(smraw);
    const uint32_t smv = smb + 65536;
    const int tid = threadIdx.x, w = tid >> 5, lane = tid & 31;
    const int q0 = blockIdx.x * 128;
    const int b = blockIdx.y;
    const int gr = b * NAG;
    const long long vbase = (long long)b * MSG * NAG;

    const int arow = ((lane >> 3) & 1) * 8 + (lane & 7);
    const int ak8  = ((lane >> 4) & 1) * 8;
    const int brow = ((lane >> 4) & 1) * 8 + (lane & 7);
    const int bk8  = ((lane >> 3) & 1) * 8;
    const int lq = lane >> 2;

    float O[16][4];
    #pragma unroll
    for (int nt = 0; nt < 16; nt++)
        #pragma unroll
        for (int j = 0; j < 4; j++) O[nt][j] = 0.f;
    float m0 = -1e30f, m1 = -1e30f, sum0 = 0.f, sum1 = 0.f;

    for (int kt = 0; kt < 4; kt++){
        const int k0 = kt * 128;

        float S[16][4];
        #pragma unroll
        for (int nt = 0; nt < 16; nt++)
            #pragma unroll
            for (int j = 0; j < 4; j++) S[nt][j] = 0.f;

        auto do_stage = [&](int t, int buf){
            uint32_t sb = smb + buf * 32768;
            if (t < 2){
                stage_tile(sb + 0,     Q, 256, gr + q0, t*64, tid);
                stage_tile(sb + 16384, K, 128, gr + k0, t*64, tid);
            } else {
                stage_tile(sb + 0,     Ob, 128, gr + q0, (t-2)*64, tid);
                stage_tile(sb + 16384, Ob, 128, gr + k0, (t-2)*64, tid);
            }
            cpa_commit();
        };

        do_stage(0, 0);
        for (int t = 0; t < 4; t++){
            if (t == 0){
                do_stage(1, 1);
                stage_tile(smv + 0,     V + vbase, NAG, 0, k0,      tid);
                stage_tile(smv + 16384, V + vbase, NAG, 0, k0 + 64, tid);
                cpa_commit();
            } else if (t + 1 < 4){
                do_stage(t + 1, (t + 1) & 1);
            }
            if (t <= 1)      cpa_wait2();
            else if (t == 2) cpa_wait1();
            else             cpa_wait0();
            __syncthreads();
            uint32_t sm = smb + (t & 1) * 32768;
            #pragma unroll
            for (int ks = 0; ks < 4; ks++){
                const int kk = ks * 16;
                uint32_t ah[4], t4[4];
                {
                    uint32_t off = (uint32_t)((w*16 + arow) * 128 + (kk + ak8) * 2);
                    uint32_t sw = off ^ ((off >> 3) & 0x70u);
                    ldsm4(ah, sm + sw);
                }
                #pragma unroll
                for (int np = 0; np < 8; np++){
                    uint32_t off = (uint32_t)((np*16 + brow) * 128 + (kk + bk8) * 2);
                    uint32_t sw = off ^ ((off >> 3) & 0x70u);
                    ldsm4(t4, sm + 16384 + sw);
                    uint32_t b0[2] = {t4[0], t4[1]}, b1[2] = {t4[2], t4[3]};
                    mma16816(S[np*2],   ah, b0);
                    mma16816(S[np*2+1], ah, b1);
                }
            }
            __syncthreads();
        }

        // ---- online softmax ----
        float mx0 = -1e30f, mx1 = -1e30f;
        #pragma unroll
        for (int nt = 0; nt < 16; nt++){
            mx0 = fmaxf(mx0, fmaxf(S[nt][0], S[nt][1]));
            mx1 = fmaxf(mx1, fmaxf(S[nt][2], S[nt][3]));
        }
        mx0 = fmaxf(mx0, __shfl_xor_sync(0xffffffffu, mx0, 1));
        mx0 = fmaxf(mx0, __shfl_xor_sync(0xffffffffu, mx0, 2));
        mx1 = fmaxf(mx1, __shfl_xor_sync(0xffffffffu, mx1, 1));
        mx1 = fmaxf(mx1, __shfl_xor_sync(0xffffffffu, mx1, 2));
        float M0 = fmaxf(m0, mx0), M1 = fmaxf(m1, mx1);
        float f0 = __expf(m0 - M0), f1 = __expf(m1 - M1);
        float rs0 = 0.f, rs1 = 0.f;
        #pragma unroll
        for (int nt = 0; nt < 16; nt++){
            float p0 = __expf(S[nt][0] - M0); S[nt][0] = p0; rs0 += p0;
            float p1 = __expf(S[nt][1] - M0); S[nt][1] = p1; rs0 += p1;
            float p2 = __expf(S[nt][2] - M1); S[nt][2] = p2; rs1 += p2;
            float p3 = __expf(S[nt][3] - M1); S[nt][3] = p3; rs1 += p3;
        }
        rs0 += __shfl_xor_sync(0xffffffffu, rs0, 1);
        rs0 += __shfl_xor_sync(0xffffffffu, rs0, 2);
        rs1 += __shfl_xor_sync(0xffffffffu, rs1, 1);
        rs1 += __shfl_xor_sync(0xffffffffu, rs1, 2);
        sum0 = sum0 * f0 + rs0;
        sum1 = sum1 * f1 + rs1;
        m0 = M0; m1 = M1;
        #pragma unroll
        for (int nt = 0; nt < 16; nt++){
            O[nt][0] *= f0; O[nt][1] *= f0; O[nt][2] *= f1; O[nt][3] *= f1;
        }

        // ---- P·V (V resident in smv) ----
        #pragma unroll
        for (int ks = 0; ks < 8; ks++){
            uint32_t ap[4];
            ap[0] = packh2(S[2*ks][0],   S[2*ks][1]);
            ap[1] = packh2(S[2*ks][2],   S[2*ks][3]);
            ap[2] = packh2(S[2*ks+1][0], S[2*ks+1][1]);
            ap[3] = packh2(S[2*ks+1][2], S[2*ks+1][3]);
            uint32_t base = (ks < 4) ? smv : smv + 16384;
            const int kk = (ks & 3) * 16;
            #pragma unroll
            for (int np = 0; np < 8; np++){
                uint32_t off = (uint32_t)((np*16 + brow) * 128 + (kk + bk8) * 2);
                uint32_t sw = off ^ ((off >> 3) & 0x70u);
                uint32_t t4[4];
                ldsm4(t4, base + sw);
                uint32_t b0[2] = {t4[0], t4[1]}, b1[2] = {t4[2], t4[3]};
                mma16816(O[np*2],   ap, b0);
                mma16816(O[np*2+1], ap, b1);
            }
        }
        __syncthreads();
    }

    float inv0 = 1.f / sum0, inv1 = 1.f / sum1;
    long long r0 = (long long)(gr + q0 + w*16 + lq) * MSG;
    long long r1 = r0 + 8 * MSG;
    #pragma unroll
    for (int nt = 0; nt < 16; nt++){
        int d = nt*8 + (lane & 3)*2;
        *(uint32_t*)(agg + r0 + d) = packh2(O[nt][0] * inv0, O[nt][1] * inv0);
        *(uint32_t*)(agg + r1 + d) = packh2(O[nt][2] * inv1, O[nt][3] * inv1);
    }
}

// ---------------- packing kernels ----------------
__global__ void pack_obs(const float* __restrict__ obs, __half* __restrict__ h)
{
    long long i = (long long)blockIdx.x * 256 + threadIdx.x;
    h[i] = __float2half_rn(obs[i]);
}
// all weights fused: [0,32768) We, [32768,98304) Wcat, [98304,131072) Wkv, [131072,229376) Wp
__global__ void pack_weights(const float* __restrict__ We,
                             const float* __restrict__ Wc, const float* __restrict__ Wn,
                             const float* __restrict__ Wb, const float* __restrict__ Wq,
                             const float* __restrict__ bc, const float* __restrict__ bn,
                             const float* __restrict__ bbp, const float* __restrict__ bq,
                             const float* __restrict__ Wk, const float* __restrict__ Wv,
                             const float* __restrict__ bk, const float* __restrict__ bv,
                             const float* __restrict__ Wp,
                             __half* __restrict__ WeT, __half* __restrict__ WcT,
                             __half* __restrict__ WkvT, __half* __restrict__ WpT,
                             float* __restrict__ bcat, float* __restrict__ bkv)
{
    int i = blockIdx.x * 256 + threadIdx.x;
    if (i < 32768){
        int n = i >> 7, k = i & 127;
        WeT[i] = __float2half_rn(We[k*256 + n]);
    } else if (i < 98304){
        int j = i - 32768;
        int n = j >> 8, k = j & 255;
        float v;
        if (n < 32)       v = Wc[k*32 + n];
        else if (n < 96)  v = Wn[k*64 + (n-32)];
        else if (n < 128) v = Wb[k*32 + (n-96)];
        else              v = Wq[k*128 + (n-128)];
        WcT[j] = __float2half_rn(v);
        if (k == 0)
            bcat[n] = (n < 32) ? bc[n] : (n < 96) ? bn[n-32] : (n < 128) ? bbp[n-96] : bq[n-128];
    } else if (i < 131072){
        int j = i - 98304;
        int n = j >> 7, k = j & 127;
        float v = (n < 128) ? Wk[k*128 + n] : Wv[k*128 + (n-128)];
        WkvT[j] = __float2half_rn(v);
        if (k == 0) bkv[n] = (n < 128) ? bk[n] : bv[n-128];
    } else {
        int j = i - 131072;
        int n = j / 384, k = j % 384;
        WpT[j] = __float2half_rn(Wp[k*256 + n]);
    }
}

// ---------------- importance + obs norm + scaled obs pack (fused) ----------------
__global__ void impnorm_kernel(const __half* __restrict__ enc,
                               const float* __restrict__ obs,
                               const float* __restrict__ Wi,
                               const float* __restrict__ bi,
                               float* __restrict__ imp,
                               __half* __restrict__ os)
{
    int row = blockIdx.x * 8 + threadIdx.y;
    int lane = threadIdx.x;
    const __half* e = enc + (long long)row * HID;
    const float* o = obs + (long long)row * OBS;
    float d = 0.f, ss = 0.f;
    float ov[4];
    #pragma unroll
    for (int i = 0; i < HID/32; i++){
        int k = lane + 32*i;
        d += __half2float(e[k]) * Wi[k];
    }
    #pragma unroll
    for (int i = 0; i < OBS/32; i++){ ov[i] = o[lane + 32*i]; ss += ov[i]*ov[i]; }
    #pragma unroll
    for (int off = 16; off; off >>= 1){
        d  += __shfl_xor_sync(0xffffffffu, d, off);
        ss += __shfl_xor_sync(0xffffffffu, ss, off);
    }
    if (lane == 0)
        imp[row] = 1.f / (1.f + expf(-(d + bi[0])));
    float s = 0.7071067811865476f / (sqrtf(ss) + 1e-8f);
    #pragma unroll
    for (int i = 0; i < OBS/32; i++){
        int k = lane + 32*i;
        os[(long long)row * OBS + k] = __float2half_rn(ov[i] * s);
    }
}

// ---------------- head ----------------
__global__ void head_kernel(const float* __restrict__ x,
                            const float* __restrict__ Wa,
                            const float* __restrict__ ba,
                            const float* __restrict__ Wcr,
                            const float* __restrict__ bcr,
                            float* __restrict__ out)
{
    int row = blockIdx.x * 8 + threadIdx.y;
    int lane = threadIdx.x;
    const float* xr = x + (long long)row * HID;
    float xv[8];
    #pragma unroll
    for (int i = 0; i < 8; i++) xv[i] = xr[lane + 32*i];
    #pragma unroll
    for (int j = 0; j < 17; j++){
        float p = 0.f;
        #pragma unroll
        for (int i = 0; i < 8; i++){
            int k = lane + 32*i;
            float w = (j < 16) ? Wa[(long long)k * NACT + j] : Wcr[k];
            p += xv[i] * w;
        }
        #pragma unroll
        for (int off = 16; off; off >>= 1) p += __shfl_down_sync(0xffffffffu, p, off);
        if (lane == 0){
            if (j < 16) out[(long long)row * NACT + j] = p + ba[j];
            else        out[(long long)ROWS * NACT + row] = p + bcr[0];
        }
    }
}

// ---------------- launch ----------------
extern "C" void kernel_launch(void* const* d_in, const int* in_sizes, int n_in,
                              void* d_out, int out_size)
{
    const float* obs = (const float*)d_in[0];
    const float* We  = (const float*)d_in[2];   const float* be  = (const float*)d_in[3];
    const float* Wc  = (const float*)d_in[4];   const float* bc  = (const float*)d_in[5];
    const float* Wn  = (const float*)d_in[6];   const float* bn  = (const float*)d_in[7];
    const float* Wb  = (const float*)d_in[8];   const float* bbp = (const float*)d_in[9];
    const float* Wi  = (const float*)d_in[10];  const float* bi  = (const float*)d_in[11];
    const float* Wq  = (const float*)d_in[12];  const float* bq  = (const float*)d_in[13];
    const float* Wk  = (const float*)d_in[14];  const float* bk  = (const float*)d_in[15];
    const float* Wv  = (const float*)d_in[16];  const float* bv  = (const float*)d_in[17];
    const float* Wp  = (const float*)d_in[18];  const float* bp  = (const float*)d_in[19];
    const float* Wa  = (const float*)d_in[20];  const float* ba  = (const float*)d_in[21];
    const float* Wcr = (const float*)d_in[22];  const float* bcr = (const float*)d_in[23];
    float* out = (float*)d_out;

    #define GA(p, sym) cudaGetSymbolAddress((void**)&p, sym)
    __half *enc,*msgq,*ks,*obh,*oss,*vt,*agg,*WeT,*WcT,*WkvT,*WpT;
    float *imp,*xb,*bcat,*bkv;
    GA(enc,g_enc); GA(msgq,g_msgq); GA(ks,g_ks); GA(obh,g_obs); GA(oss,g_obss);
    GA(vt,g_vT); GA(agg,g_agg); GA(imp,g_imp); GA(xb,g_x);
    GA(bcat,g_bcat); GA(bkv,g_bkv);
    GA(WeT,g_WeT); GA(WcT,g_WcatT); GA(WkvT,g_WkvT); GA(WpT,g_WpT);
    #undef GA

    cudaFuncSetAttribute(bf_gemm,      cudaFuncAttributeMaxDynamicSharedMemorySize, SMEM_GEMM);
    cudaFuncSetAttribute(flash_kernel, cudaFuncAttributeMaxDynamicSharedMemorySize, SMEM_FLASH);

    OutD z = {};

    // packs (obs + all weights)
    pack_obs    <<<ROWS*OBS/256, 256>>>(obs, obh);
    pack_weights<<<896, 256>>>(We, Wc, Wn, Wb, Wq, bc, bn, bbp, bq,
                               Wk, Wv, bk, bv, Wp, WeT, WcT, WkvT, WpT, bcat, bkv);

    // enc = relu(obs @ We + be) -> fp16
    {
        OutD o = z; o.h = enc; o.factor = 1.f; o.ldc = 256; o.relu = 1;
        bf_gemm<<<dim3(4,256,1), 512, SMEM_GEMM>>>(obh, OBS, OBS, nullptr, 0, OBS,
                                                   WeT, OBS, be, 0, 0, 4, o, o);
    }
    // imp + scaled obs pack (fused)
    impnorm_kernel<<<ROWS/8, dim3(32,8)>>>(enc, obs, Wi, bi, imp, oss);
    // msgq = enc @ Wcat + bcat; Q (cols>=128) scaled by imp/sqrt(128)
    {
        OutD o0 = z; o0.h = msgq; o0.factor = 1.f; o0.ldc = 256;
        OutD o1 = o0; o1.rowscale = imp; o1.factor = 0.08838834764831845f;
        bf_gemm<<<dim3(4,256,1), 512, SMEM_GEMM>>>(enc, 256, 256, nullptr, 0, 256,
                                                   WcT, 256, bcat, 0, 0, 2, o0, o1);
    }
    // kv: K (cols<128) scaled by imp -> fp16; V (cols>=128) -> transposed vT
    {
        OutD o0 = z; o0.h = ks; o0.rowscale = imp; o0.factor = 1.f; o0.ldc = 128;
        OutD o1 = z; o1.h = vt; o1.factor = 1.f; o1.colsub = 128; o1.vtrans = 1;
        bf_gemm<<<dim3(4,256,1), 512, SMEM_GEMM>>>(msgq, 256, 128, nullptr, 0, 128,
                                                   WkvT, 128, bkv, 0, 0, 2, o0, o1);
    }
    // flash attention -> agg fp16
    flash_kernel<<<dim3(4, BSZ), 256, SMEM_FLASH>>>(msgq + 128, ks, oss, vt, agg);
    // x = relu([enc|agg] @ Wp + bp) -> fp32
    {
        OutD o = z; o.f = xb; o.factor = 1.f; o.ldc = 256; o.relu = 1;
        bf_gemm<<<dim3(4,256,1), 512, SMEM_GEMM>>>(enc, 256, 256, agg, 128, 384,
                                                   WpT, 384, bp, 0, 0, 4, o, o);
    }
    // heads
    head_kernel<<<ROWS/8, dim3(32,8)>>>(xb, Wa, ba, Wcr, bcr, out);
}